// round 7
// baseline (speedup 1.0000x reference)
#include <cuda_runtime.h>
#include <cuda_bf16.h>
#include <math.h>
#include <stdint.h>

// ---------------------------------------------------------------------------
// Problem constants
// ---------------------------------------------------------------------------
#define BATCH   2
#define SEQ     2048
#define DMODEL  512
#define NHEADS  8
#define HEADDIM 64
#define DFF     2048
#define MTOT    (BATCH * SEQ)          // 4096 rows
#define LN_EPS  1e-5f

typedef __nv_bfloat16 bf16;

// ---------------------------------------------------------------------------
// Scratch (static device globals; no allocations allowed)
// ---------------------------------------------------------------------------
__device__ __align__(16) bf16 g_xh [MTOT * DMODEL], g_xl [MTOT * DMODEL];
__device__ __align__(16) bf16 g_Wqh[DMODEL * DMODEL], g_Wql[DMODEL * DMODEL];
__device__ __align__(16) bf16 g_Wkh[DMODEL * DMODEL], g_Wkl[DMODEL * DMODEL];
__device__ __align__(16) bf16 g_Wvh[DMODEL * DMODEL], g_Wvl[DMODEL * DMODEL];
__device__ __align__(16) bf16 g_Woh[DMODEL * DMODEL], g_Wol[DMODEL * DMODEL];
__device__ __align__(16) bf16 g_W1h[DMODEL * DFF],    g_W1l[DMODEL * DFF];
__device__ __align__(16) bf16 g_W2h[DFF * DMODEL],    g_W2l[DFF * DMODEL];
__device__ __align__(16) bf16 g_Qh [MTOT * DMODEL], g_Ql [MTOT * DMODEL];
__device__ __align__(16) bf16 g_Kh [MTOT * DMODEL], g_Kl [MTOT * DMODEL];
__device__ __align__(16) bf16 g_Vh [MTOT * DMODEL], g_Vl [MTOT * DMODEL];
__device__ __align__(16) bf16 g_Ch [MTOT * DMODEL], g_Cl [MTOT * DMODEL];
__device__ __align__(16) bf16 g_Hh [MTOT * DMODEL], g_Hl [MTOT * DMODEL];
__device__ __align__(16) bf16 g_Fh [MTOT * DFF],    g_Fl [MTOT * DFF];
__device__ float g_ATT[MTOT * DMODEL];
__device__ float g_H  [MTOT * DMODEL];
__device__ float g_TMP[MTOT * DMODEL];

// ---------------------------------------------------------------------------
// Helpers
// ---------------------------------------------------------------------------
__device__ __forceinline__ uint32_t smem_u32(const void* p) {
    uint32_t a;
    asm("{ .reg .u64 t; cvta.to.shared.u64 t, %1; cvt.u32.u64 %0, t; }"
        : "=r"(a) : "l"(p));
    return a;
}

__device__ __forceinline__ void cp16(uint32_t s, const void* g) {
    asm volatile("cp.async.cg.shared.global [%0], [%1], 16;" :: "r"(s), "l"(g));
}
#define CP_COMMIT() asm volatile("cp.async.commit_group;")
#define CP_WAIT(n)  asm volatile("cp.async.wait_group %0;" :: "n"(n))

__device__ __forceinline__ void mma_bf16(float* c, const uint32_t* a, const uint32_t* b) {
    asm volatile(
        "mma.sync.aligned.m16n8k16.row.col.f32.bf16.bf16.f32 "
        "{%0,%1,%2,%3}, {%4,%5,%6,%7}, {%8,%9}, {%0,%1,%2,%3};"
        : "+f"(c[0]), "+f"(c[1]), "+f"(c[2]), "+f"(c[3])
        : "r"(a[0]), "r"(a[1]), "r"(a[2]), "r"(a[3]), "r"(b[0]), "r"(b[1]));
}

__device__ __forceinline__ void ldsm_x4(uint32_t* r, uint32_t addr) {
    asm volatile("ldmatrix.sync.aligned.m8n8.x4.shared.b16 {%0,%1,%2,%3}, [%4];"
                 : "=r"(r[0]), "=r"(r[1]), "=r"(r[2]), "=r"(r[3]) : "r"(addr));
}
__device__ __forceinline__ void ldsm_x4t(uint32_t* r, uint32_t addr) {
    asm volatile("ldmatrix.sync.aligned.m8n8.x4.trans.shared.b16 {%0,%1,%2,%3}, [%4];"
                 : "=r"(r[0]), "=r"(r[1]), "=r"(r[2]), "=r"(r[3]) : "r"(addr));
}
__device__ __forceinline__ void ldsm_x2t(uint32_t* r, uint32_t addr) {
    asm volatile("ldmatrix.sync.aligned.m8n8.x2.trans.shared.b16 {%0,%1}, [%2];"
                 : "=r"(r[0]), "=r"(r[1]) : "r"(addr));
}

__device__ __forceinline__ uint32_t pack_bf16(float a, float b) {
    __nv_bfloat162 t = __floats2bfloat162_rn(a, b);
    return *(uint32_t*)&t;
}

__device__ __forceinline__ void split_store2(bf16* Ch, bf16* Cl, size_t off,
                                             float a, float b) {
    float ha = __bfloat162float(__float2bfloat16_rn(a));
    float hb = __bfloat162float(__float2bfloat16_rn(b));
    *(uint32_t*)(Ch + off) = pack_bf16(ha, hb);
    *(uint32_t*)(Cl + off) = pack_bf16(a - ha, b - hb);
}

// ---------------------------------------------------------------------------
// Splitter: fp32 -> (hi, lo) bf16 planes for x and all 6 weight matrices.
// ---------------------------------------------------------------------------
__global__ void __launch_bounds__(256)
split_inputs(const float* __restrict__ x,  const float* __restrict__ Wq,
             const float* __restrict__ Wk, const float* __restrict__ Wv,
             const float* __restrict__ Wo, const float* __restrict__ W1,
             const float* __restrict__ W2)
{
    const float* src; bf16 *ph, *pl; int n4;
    switch (blockIdx.y) {
        case 0: src = x;  ph = g_xh;  pl = g_xl;  n4 = MTOT * DMODEL / 4; break;
        case 1: src = Wq; ph = g_Wqh; pl = g_Wql; n4 = DMODEL * DMODEL / 4; break;
        case 2: src = Wk; ph = g_Wkh; pl = g_Wkl; n4 = DMODEL * DMODEL / 4; break;
        case 3: src = Wv; ph = g_Wvh; pl = g_Wvl; n4 = DMODEL * DMODEL / 4; break;
        case 4: src = Wo; ph = g_Woh; pl = g_Wol; n4 = DMODEL * DMODEL / 4; break;
        case 5: src = W1; ph = g_W1h; pl = g_W1l; n4 = DMODEL * DFF / 4;    break;
        default:src = W2; ph = g_W2h; pl = g_W2l; n4 = DFF * DMODEL / 4;    break;
    }
    for (int i = blockIdx.x * 256 + threadIdx.x; i < n4; i += gridDim.x * 256) {
        float4 v = ((const float4*)src)[i];
        float hx = __bfloat162float(__float2bfloat16_rn(v.x));
        float hy = __bfloat162float(__float2bfloat16_rn(v.y));
        float hz = __bfloat162float(__float2bfloat16_rn(v.z));
        float hw = __bfloat162float(__float2bfloat16_rn(v.w));
        uint2 hv, lv;
        hv.x = pack_bf16(hx, hy);             hv.y = pack_bf16(hz, hw);
        lv.x = pack_bf16(v.x - hx, v.y - hy); lv.y = pack_bf16(v.z - hz, v.w - hw);
        ((uint2*)ph)[i] = hv;
        ((uint2*)pl)[i] = lv;
    }
}

// ---------------------------------------------------------------------------
// Pipelined bf16 tensor-core GEMM: 3-stage cp.async, single sync/iter.
// Tile 64x128, BK=32, 256 threads (8 warps, 2x4, warp tile 32x32).
// ---------------------------------------------------------------------------
#define G_APL (64 * 80)     // A plane bytes
#define G_BPL (32 * 272)    // B plane bytes
#define G_STG (2 * G_APL + 2 * G_BPL)   // 27648
#define G_NST 3
#define GEMM_SMEM (G_NST * G_STG)       // 82944

template <int OMODE, bool RELU>
__device__ __forceinline__ void gemm64_body(
    const bf16* __restrict__ Ah, const bf16* __restrict__ Al,
    const bf16* __restrict__ Bh, const bf16* __restrict__ Bl,
    const float* __restrict__ bias,
    float* __restrict__ Cf, bf16* __restrict__ Ch, bf16* __restrict__ Cl,
    int N, int K, float scale, int bx, int by)
{
    extern __shared__ __align__(16) char dy[];
    const int tid    = threadIdx.x;
    const int wid    = tid >> 5;
    const int lane   = tid & 31;
    const int warp_m = wid & 1;
    const int warp_n = wid >> 1;
    const int gid    = lane >> 2;
    const int tig    = lane & 3;
    const uint32_t sb = smem_u32(dy);

    float acc[2][4][4];
#pragma unroll
    for (int mt = 0; mt < 2; mt++)
#pragma unroll
        for (int nt = 0; nt < 4; nt++)
#pragma unroll
            for (int e = 0; e < 4; e++) acc[mt][nt][e] = 0.f;

    const int ra = tid >> 2, ca = tid & 3;
    const uint32_t aSm = sb + (uint32_t)ra * 80 + (uint32_t)ca * 16;
    const size_t   aGm = (size_t)(by * 64 + ra) * K + ca * 8;
    const int rb = tid >> 4, cb = tid & 15;
    const uint32_t bSm = sb + 2u * G_APL + (uint32_t)rb * 272 + (uint32_t)cb * 16;
    const size_t   bGm = (size_t)rb * N + bx * 128 + cb * 8;

    const int NKC = K >> 5;

    auto issue = [&](int kc) {
        const uint32_t so = (uint32_t)(kc % G_NST) * G_STG;
        cp16(aSm + so,          Ah + aGm + kc * 32);
        cp16(aSm + so + G_APL,  Al + aGm + kc * 32);
        const size_t g0 = bGm + (size_t)(kc * 32) * N;
        cp16(bSm + so,          Bh + g0);
        cp16(bSm + so + G_BPL,  Bl + g0);
        const size_t g1 = g0 + (size_t)16 * N;
        cp16(bSm + so + 16u * 272,         Bh + g1);
        cp16(bSm + so + G_BPL + 16u * 272, Bl + g1);
        CP_COMMIT();
    };

    issue(0);
    if (NKC > 1) issue(1); else CP_COMMIT();

    const uint32_t aOff = sb + (uint32_t)(warp_m * 32 + (lane & 15)) * 80
                        + (uint32_t)((lane >> 4) * 8) * 2;
    const uint32_t bOff = sb + 2u * G_APL + (uint32_t)(lane & 15) * 272
                        + (uint32_t)(warp_n * 32) * 2;

    for (int kc = 0; kc < NKC; kc++) {
        CP_WAIT(1);
        __syncthreads();
        if (kc + 2 < NKC) issue(kc + 2); else CP_COMMIT();

        const uint32_t so = (uint32_t)(kc % G_NST) * G_STG;
#pragma unroll
        for (int ks = 0; ks < 2; ks++) {
            uint32_t ah[2][4], al[2][4];
#pragma unroll
            for (int mt = 0; mt < 2; mt++) {
                uint32_t ao = so + (uint32_t)(mt * 16) * 80 + (uint32_t)(ks * 16) * 2;
                ldsm_x4(ah[mt], aOff + ao);
                ldsm_x4(al[mt], aOff + ao + G_APL);
            }
#pragma unroll
            for (int nt = 0; nt < 4; nt++) {
                uint32_t bo = so + (uint32_t)(ks * 16) * 272 + (uint32_t)(nt * 8) * 2;
                uint32_t bh[2], bl[2];
                ldsm_x2t(bh, bOff + bo);
                ldsm_x2t(bl, bOff + bo + G_BPL);
#pragma unroll
                for (int mt = 0; mt < 2; mt++) {
                    mma_bf16(acc[mt][nt], ah[mt], bh);
                    mma_bf16(acc[mt][nt], ah[mt], bl);
                    mma_bf16(acc[mt][nt], al[mt], bh);
                }
            }
        }
    }

    const int m0 = by * 64 + warp_m * 32;
    const int n0 = bx * 128 + warp_n * 32;
#pragma unroll
    for (int nt = 0; nt < 4; nt++) {
        const int col = n0 + nt * 8 + tig * 2;
        const float b0 = bias ? bias[col] : 0.f;
        const float b1 = bias ? bias[col + 1] : 0.f;
#pragma unroll
        for (int mt = 0; mt < 2; mt++) {
            const int row0 = m0 + mt * 16 + gid;
            float v00 = acc[mt][nt][0] + b0, v01 = acc[mt][nt][1] + b1;
            float v10 = acc[mt][nt][2] + b0, v11 = acc[mt][nt][3] + b1;
            if (RELU) {
                v00 = fmaxf(v00, 0.f); v01 = fmaxf(v01, 0.f);
                v10 = fmaxf(v10, 0.f); v11 = fmaxf(v11, 0.f);
            }
            v00 *= scale; v01 *= scale; v10 *= scale; v11 *= scale;
            if (OMODE == 0) {
                *(float2*)(Cf + (size_t)row0 * N + col)       = make_float2(v00, v01);
                *(float2*)(Cf + (size_t)(row0 + 8) * N + col) = make_float2(v10, v11);
            } else {
                split_store2(Ch, Cl, (size_t)row0 * N + col,       v00, v01);
                split_store2(Ch, Cl, (size_t)(row0 + 8) * N + col, v10, v11);
            }
        }
    }
}

__global__ void __launch_bounds__(256)
gemm_qkv_bias(const float* __restrict__ bq, const float* __restrict__ bk,
              const float* __restrict__ bv)
{
    const int z = blockIdx.z;
    const bf16 *Bh_, *Bl_; bf16 *Oh, *Ol; const float* bias; float scale;
    if (z == 0)      { Bh_ = g_Wqh; Bl_ = g_Wql; Oh = g_Qh; Ol = g_Ql; bias = bq; scale = 0.125f; }
    else if (z == 1) { Bh_ = g_Wkh; Bl_ = g_Wkl; Oh = g_Kh; Ol = g_Kl; bias = bk; scale = 1.f; }
    else             { Bh_ = g_Wvh; Bl_ = g_Wvl; Oh = g_Vh; Ol = g_Vl; bias = bv; scale = 1.f; }
    gemm64_body<1, false>(g_xh, g_xl, Bh_, Bl_, bias, nullptr, Oh, Ol,
                          DMODEL, DMODEL, scale, blockIdx.x, blockIdx.y);
}

template <int OMODE, bool RELU>
__global__ void __launch_bounds__(256)
gemm_sp(const bf16* __restrict__ Ah, const bf16* __restrict__ Al,
        const bf16* __restrict__ Bh, const bf16* __restrict__ Bl,
        const float* __restrict__ bias,
        float* __restrict__ Cf, bf16* __restrict__ Ch, bf16* __restrict__ Cl,
        int N, int K)
{
    gemm64_body<OMODE, RELU>(Ah, Al, Bh, Bl, bias, Cf, Ch, Cl,
                             N, K, 1.f, blockIdx.x, blockIdx.y);
}

// ---------------------------------------------------------------------------
// Pipelined tensor-core flash attention: BQ=128 (8 warps), 3-stage KV
// cp.async pipeline, single sync/iter, no online softmax.
// grid = (SEQ/128, BATCH*NHEADS), 256 threads.
// smem: Q hi/lo 128x72 + 3 stages x (K,V hi/lo 32x72) = 92160 B.
// ---------------------------------------------------------------------------
#define FA_ROW   144
#define FA_QPL   (128 * FA_ROW)      // 18432
#define FA_KVPL  (32 * FA_ROW)       // 4608
#define FA_KVST  (4 * FA_KVPL)       // 18432 per stage
#define FA_BASE  (2 * FA_QPL)        // 36864
#define FA_NST   3
#define FA_SMEM  (FA_BASE + FA_NST * FA_KVST)   // 92160

__global__ void __launch_bounds__(256)
flash_attn_mma()
{
    constexpr int BKV = 32, DH = HEADDIM, DM = DMODEL;
    extern __shared__ __align__(16) char dy[];

    const int tid  = threadIdx.x;
    const int wid  = tid >> 5;
    const int lane = tid & 31;
    const int g    = lane >> 2;
    const int tig  = lane & 3;
    const uint32_t sb = smem_u32(dy);

    const int bh = blockIdx.y;
    const int b  = bh >> 3;
    const int h  = bh & 7;
    const int q0 = blockIdx.x * 128;

    const size_t hoff = (size_t)b * SEQ * DM + h * DH;

    // KV issue: tile 32x64 per plane = 256 uint4 over 256 threads (1 each/plane)
    const int kvr = tid >> 3, kvc = (tid & 7);
    auto issue_kv = [&](int it) {
        const uint32_t so = FA_BASE + (uint32_t)(it % FA_NST) * FA_KVST;
        uint32_t s = sb + so + (uint32_t)kvr * FA_ROW + (uint32_t)kvc * 16;
        size_t gm = hoff + (size_t)(it * BKV + kvr) * DM + kvc * 8;
        cp16(s,               g_Kh + gm);
        cp16(s + FA_KVPL,     g_Kl + gm);
        cp16(s + 2 * FA_KVPL, g_Vh + gm);
        cp16(s + 3 * FA_KVPL, g_Vl + gm);
        CP_COMMIT();
    };

    issue_kv(0);
    issue_kv(1);

    // Q tile load (pre-scaled planes): 128x64 per plane = 1024 uint4
#pragma unroll
    for (int j = 0; j < 4; j++) {
        int i = j * 256 + tid;
        int r = i >> 3, c8 = (i & 7) * 8;
        size_t off = hoff + (size_t)(q0 + r) * DM + c8;
        *(uint4*)(dy + (uint32_t)r * FA_ROW + c8 * 2)          = *(const uint4*)(g_Qh + off);
        *(uint4*)(dy + FA_QPL + (uint32_t)r * FA_ROW + c8 * 2) = *(const uint4*)(g_Ql + off);
    }

    const uint32_t qRowA = (uint32_t)(wid * 16 + (lane & 8) + (lane & 7));
    const uint32_t aColO = (uint32_t)((lane & 16) >> 1);
    const uint32_t qBaseH = sb + qRowA * FA_ROW + aColO * 2;
    const uint32_t qBaseL = qBaseH + FA_QPL;
    const uint32_t kRowO = (uint32_t)(((lane & 16) >> 1) + (lane & 7));
    const uint32_t kColO = (uint32_t)(lane & 8);
    const uint32_t kBase = sb + FA_BASE + kRowO * FA_ROW + kColO * 2;
    const uint32_t vRowO = (uint32_t)((lane & 8) + (lane & 7));
    const uint32_t vColO = (uint32_t)((lane & 16) >> 1);
    const uint32_t vBase = sb + FA_BASE + 2 * FA_KVPL + vRowO * FA_ROW + vColO * 2;

    float l_t = 0.f, l_b = 0.f;
    float O[8][4];
#pragma unroll
    for (int dt = 0; dt < 8; dt++)
#pragma unroll
        for (int e = 0; e < 4; e++) O[dt][e] = 0.f;

    constexpr int NIT = SEQ / BKV;   // 64
    for (int it = 0; it < NIT; it++) {
        CP_WAIT(1);
        __syncthreads();
        if (it + 2 < NIT) issue_kv(it + 2); else CP_COMMIT();

        const uint32_t so = (uint32_t)(it % FA_NST) * FA_KVST;

        // ---- scores ----
        float S[4][4];
#pragma unroll
        for (int t = 0; t < 4; t++)
#pragma unroll
            for (int e = 0; e < 4; e++) S[t][e] = 0.f;

#pragma unroll
        for (int ks = 0; ks < 4; ks++) {
            uint32_t qh[4], ql[4];
            ldsm_x4(qh, qBaseH + (uint32_t)(ks * 16) * 2);
            ldsm_x4(ql, qBaseL + (uint32_t)(ks * 16) * 2);
#pragma unroll
            for (int np = 0; np < 2; np++) {
                uint32_t kbh[4], kbl[4];
                uint32_t ro = so + (uint32_t)(np * 16) * FA_ROW + (uint32_t)(ks * 16) * 2;
                ldsm_x4(kbh, kBase + ro);
                ldsm_x4(kbl, kBase + ro + FA_KVPL);
                mma_bf16(S[2 * np],     qh, kbh);
                mma_bf16(S[2 * np],     qh, kbl);
                mma_bf16(S[2 * np],     ql, kbh);
                mma_bf16(S[2 * np + 1], qh, kbh + 2);
                mma_bf16(S[2 * np + 1], qh, kbl + 2);
                mma_bf16(S[2 * np + 1], ql, kbh + 2);
            }
        }

        // ---- P = exp(S), accumulate row sums ----
#pragma unroll
        for (int t = 0; t < 4; t++) {
            S[t][0] = __expf(S[t][0]);
            S[t][1] = __expf(S[t][1]);
            S[t][2] = __expf(S[t][2]);
            S[t][3] = __expf(S[t][3]);
            l_t += S[t][0] + S[t][1];
            l_b += S[t][2] + S[t][3];
        }

        // ---- P @ V ----
#pragma unroll
        for (int ks = 0; ks < 2; ks++) {
            uint32_t Ph[4], Pl[4];
#pragma unroll
            for (int half = 0; half < 2; half++) {
                const int t = 2 * ks + half;
                float h0 = __bfloat162float(__float2bfloat16_rn(S[t][0]));
                float h1 = __bfloat162float(__float2bfloat16_rn(S[t][1]));
                float h2 = __bfloat162float(__float2bfloat16_rn(S[t][2]));
                float h3 = __bfloat162float(__float2bfloat16_rn(S[t][3]));
                Ph[2 * half + 0] = pack_bf16(h0, h1);
                Ph[2 * half + 1] = pack_bf16(h2, h3);
                Pl[2 * half + 0] = pack_bf16(S[t][0] - h0, S[t][1] - h1);
                Pl[2 * half + 1] = pack_bf16(S[t][2] - h2, S[t][3] - h3);
            }
#pragma unroll
            for (int dp = 0; dp < 4; dp++) {
                uint32_t vbh[4], vbl[4];
                uint32_t off = so + (uint32_t)(ks * 16) * FA_ROW + (uint32_t)(dp * 16) * 2;
                ldsm_x4t(vbh, vBase + off);
                ldsm_x4t(vbl, vBase + off + FA_KVPL);
                mma_bf16(O[2 * dp],     Ph, vbh);
                mma_bf16(O[2 * dp],     Ph, vbl);
                mma_bf16(O[2 * dp],     Pl, vbh);
                mma_bf16(O[2 * dp + 1], Ph, vbh + 2);
                mma_bf16(O[2 * dp + 1], Ph, vbl + 2);
                mma_bf16(O[2 * dp + 1], Pl, vbh + 2);
            }
        }
    }

    // ---- final row-sum reduce, normalize, split-store CTX planes ----
    l_t += __shfl_xor_sync(0xffffffffu, l_t, 1);
    l_t += __shfl_xor_sync(0xffffffffu, l_t, 2);
    l_b += __shfl_xor_sync(0xffffffffu, l_b, 1);
    l_b += __shfl_xor_sync(0xffffffffu, l_b, 2);
    const float inv_t = 1.f / l_t;
    const float inv_b = 1.f / l_b;
    const int row_t = b * SEQ + q0 + wid * 16 + g;
#pragma unroll
    for (int dt = 0; dt < 8; dt++) {
        const int col = h * DH + dt * 8 + tig * 2;
        split_store2(g_Ch, g_Cl, (size_t)row_t * DM + col,
                     O[dt][0] * inv_t, O[dt][1] * inv_t);
        split_store2(g_Ch, g_Cl, (size_t)(row_t + 8) * DM + col,
                     O[dt][2] * inv_b, O[dt][3] * inv_b);
    }
}

// ---------------------------------------------------------------------------
// Fused residual-add + LayerNorm over D=512; optional split-plane output.
// ---------------------------------------------------------------------------
template <bool SPLITOUT>
__global__ void __launch_bounds__(256)
add_ln(const float* __restrict__ A, const float* __restrict__ Bm,
       const float* __restrict__ g, const float* __restrict__ be,
       float* __restrict__ out, bf16* __restrict__ oh, bf16* __restrict__ ol)
{
    __shared__ float sh[16];
    const int row = blockIdx.x;
    const int t   = threadIdx.x;
    const float* a = A  + (size_t)row * DMODEL;
    const float* b = Bm + (size_t)row * DMODEL;

    float v0 = a[t]       + b[t];
    float v1 = a[t + 256] + b[t + 256];
    float s = v0 + v1;
    float q = v0 * v0 + v1 * v1;
#pragma unroll
    for (int ofs = 16; ofs; ofs >>= 1) {
        s += __shfl_xor_sync(0xffffffffu, s, ofs);
        q += __shfl_xor_sync(0xffffffffu, q, ofs);
    }
    if ((t & 31) == 0) { sh[t >> 5] = s; sh[8 + (t >> 5)] = q; }
    __syncthreads();
    if (t < 32) {
        s = (t < 8) ? sh[t]     : 0.f;
        q = (t < 8) ? sh[8 + t] : 0.f;
#pragma unroll
        for (int ofs = 4; ofs; ofs >>= 1) {
            s += __shfl_xor_sync(0xffffffffu, s, ofs);
            q += __shfl_xor_sync(0xffffffffu, q, ofs);
        }
        if (t == 0) {
            float mean = s * (1.f / DMODEL);
            float var  = q * (1.f / DMODEL) - mean * mean;
            sh[0] = mean;
            sh[1] = rsqrtf(var + LN_EPS);
        }
    }
    __syncthreads();
    float mean = sh[0], rstd = sh[1];
    float y0 = (v0 - mean) * rstd * g[t]       + be[t];
    float y1 = (v1 - mean) * rstd * g[t + 256] + be[t + 256];
    out[(size_t)row * DMODEL + t]       = y0;
    out[(size_t)row * DMODEL + t + 256] = y1;
    if (SPLITOUT) {
        float h0 = __bfloat162float(__float2bfloat16_rn(y0));
        float h1 = __bfloat162float(__float2bfloat16_rn(y1));
        oh[(size_t)row * DMODEL + t]       = __float2bfloat16_rn(y0);
        ol[(size_t)row * DMODEL + t]       = __float2bfloat16_rn(y0 - h0);
        oh[(size_t)row * DMODEL + t + 256] = __float2bfloat16_rn(y1);
        ol[(size_t)row * DMODEL + t + 256] = __float2bfloat16_rn(y1 - h1);
    }
}

// ---------------------------------------------------------------------------
// kernel_launch
// Inputs: x Wq bq Wk bk Wv bv Wo bo W1 b1 W2 b2 g1 be1 g2 be2
// ---------------------------------------------------------------------------
extern "C" void kernel_launch(void* const* d_in, const int* in_sizes, int n_in,
                              void* d_out, int out_size)
{
    const float* x   = (const float*)d_in[0];
    const float* Wq  = (const float*)d_in[1];
    const float* bq  = (const float*)d_in[2];
    const float* Wk  = (const float*)d_in[3];
    const float* bk  = (const float*)d_in[4];
    const float* Wv  = (const float*)d_in[5];
    const float* bv  = (const float*)d_in[6];
    const float* Wo  = (const float*)d_in[7];
    const float* bo  = (const float*)d_in[8];
    const float* W1  = (const float*)d_in[9];
    const float* b1  = (const float*)d_in[10];
    const float* W2  = (const float*)d_in[11];
    const float* b2  = (const float*)d_in[12];
    const float* g1  = (const float*)d_in[13];
    const float* be1 = (const float*)d_in[14];
    const float* g2  = (const float*)d_in[15];
    const float* be2 = (const float*)d_in[16];
    float* out = (float*)d_out;

    float *ATT, *H, *TMP;
    bf16 *Ch, *Cl, *Hh, *Hl, *Fh, *Fl;
    bf16 *Woh, *Wol, *W1h, *W1l, *W2h, *W2l;
    cudaGetSymbolAddress((void**)&ATT, g_ATT);
    cudaGetSymbolAddress((void**)&H,   g_H);
    cudaGetSymbolAddress((void**)&TMP, g_TMP);
    cudaGetSymbolAddress((void**)&Ch,  g_Ch);
    cudaGetSymbolAddress((void**)&Cl,  g_Cl);
    cudaGetSymbolAddress((void**)&Hh,  g_Hh);
    cudaGetSymbolAddress((void**)&Hl,  g_Hl);
    cudaGetSymbolAddress((void**)&Fh,  g_Fh);
    cudaGetSymbolAddress((void**)&Fl,  g_Fl);
    cudaGetSymbolAddress((void**)&Woh, g_Woh);
    cudaGetSymbolAddress((void**)&Wol, g_Wol);
    cudaGetSymbolAddress((void**)&W1h, g_W1h);
    cudaGetSymbolAddress((void**)&W1l, g_W1l);
    cudaGetSymbolAddress((void**)&W2h, g_W2h);
    cudaGetSymbolAddress((void**)&W2l, g_W2l);

    static bool attr_done = false;
    if (!attr_done) {
        cudaFuncSetAttribute(gemm_qkv_bias,
                             cudaFuncAttributeMaxDynamicSharedMemorySize, GEMM_SMEM);
        cudaFuncSetAttribute(gemm_sp<0, false>,
                             cudaFuncAttributeMaxDynamicSharedMemorySize, GEMM_SMEM);
        cudaFuncSetAttribute(gemm_sp<1, true>,
                             cudaFuncAttributeMaxDynamicSharedMemorySize, GEMM_SMEM);
        cudaFuncSetAttribute(flash_attn_mma,
                             cudaFuncAttributeMaxDynamicSharedMemorySize, FA_SMEM);
        attr_done = true;
    }

    dim3 gqkv (DMODEL / 128, MTOT / 64, 3);   // (4, 64, 3)
    dim3 gproj(DMODEL / 128, MTOT / 64);      // (4, 64)
    dim3 gff1 (DFF    / 128, MTOT / 64);      // (16, 64)

    // 0) split x + weights into bf16 hi/lo planes
    split_inputs<<<dim3(512, 7), 256>>>(x, Wq, Wk, Wv, Wo, W1, W2);

    // 1) QKV projections (Q pre-scaled by 1/8)
    gemm_qkv_bias<<<gqkv, 256, GEMM_SMEM>>>(bq, bk, bv);

    // 2) attention -> CTX planes
    flash_attn_mma<<<dim3(SEQ / 128, BATCH * NHEADS), 256, FA_SMEM>>>();

    // 3) output projection -> ATT fp32
    gemm_sp<0, false><<<gproj, 256, GEMM_SMEM>>>(Ch, Cl, Woh, Wol, bo,
                                                 ATT, nullptr, nullptr, DMODEL, DMODEL);

    // 4) residual + LN1 -> H fp32 + planes
    add_ln<true><<<MTOT, 256>>>(x, ATT, g1, be1, H, Hh, Hl);

    // 5) FFN up + ReLU -> FF planes
    gemm_sp<1, true><<<gff1, 256, GEMM_SMEM>>>(Hh, Hl, W1h, W1l, b1,
                                               nullptr, Fh, Fl, DFF, DMODEL);

    // 6) FFN down -> TMP fp32
    gemm_sp<0, false><<<gproj, 256, GEMM_SMEM>>>(Fh, Fl, W2h, W2l, b2,
                                                 TMP, nullptr, nullptr, DMODEL, DFF);

    // 7) residual + LN2 -> out
    add_ln<false><<<MTOT, 256>>>(H, TMP, g2, be2, out, nullptr, nullptr);
}

// round 9
// speedup vs baseline: 1.0831x; 1.0831x over previous
#include <cuda_runtime.h>
#include <cuda_bf16.h>
#include <math.h>
#include <stdint.h>

// ---------------------------------------------------------------------------
// Problem constants
// ---------------------------------------------------------------------------
#define BATCH   2
#define SEQ     2048
#define DMODEL  512
#define NHEADS  8
#define HEADDIM 64
#define DFF     2048
#define MTOT    (BATCH * SEQ)          // 4096 rows
#define LN_EPS  1e-5f

typedef __nv_bfloat16 bf16;

// ---------------------------------------------------------------------------
// Scratch (static device globals; no allocations allowed)
// ---------------------------------------------------------------------------
__device__ __align__(16) bf16 g_xh [MTOT * DMODEL], g_xl [MTOT * DMODEL];
__device__ __align__(16) bf16 g_Wqh[DMODEL * DMODEL], g_Wql[DMODEL * DMODEL];
__device__ __align__(16) bf16 g_Wkh[DMODEL * DMODEL], g_Wkl[DMODEL * DMODEL];
__device__ __align__(16) bf16 g_Wvh[DMODEL * DMODEL], g_Wvl[DMODEL * DMODEL];
__device__ __align__(16) bf16 g_Woh[DMODEL * DMODEL], g_Wol[DMODEL * DMODEL];
__device__ __align__(16) bf16 g_W1h[DMODEL * DFF],    g_W1l[DMODEL * DFF];
__device__ __align__(16) bf16 g_W2h[DFF * DMODEL],    g_W2l[DFF * DMODEL];
__device__ __align__(16) bf16 g_Qh [MTOT * DMODEL], g_Ql [MTOT * DMODEL];
__device__ __align__(16) bf16 g_Kh [MTOT * DMODEL], g_Kl [MTOT * DMODEL];
__device__ __align__(16) bf16 g_Vh [MTOT * DMODEL], g_Vl [MTOT * DMODEL];
__device__ __align__(16) bf16 g_Ch [MTOT * DMODEL], g_Cl [MTOT * DMODEL];
__device__ __align__(16) bf16 g_Hh [MTOT * DMODEL], g_Hl [MTOT * DMODEL];
__device__ __align__(16) bf16 g_Fh [MTOT * DFF],    g_Fl [MTOT * DFF];
__device__ float g_PS[4 * MTOT * DMODEL];   // split-K partial sums
__device__ float g_H [MTOT * DMODEL];

// ---------------------------------------------------------------------------
// Helpers
// ---------------------------------------------------------------------------
__device__ __forceinline__ uint32_t smem_u32(const void* p) {
    uint32_t a;
    asm("{ .reg .u64 t; cvta.to.shared.u64 t, %1; cvt.u32.u64 %0, t; }"
        : "=r"(a) : "l"(p));
    return a;
}

__device__ __forceinline__ void cp16(uint32_t s, const void* g) {
    asm volatile("cp.async.cg.shared.global [%0], [%1], 16;" :: "r"(s), "l"(g));
}
#define CP_COMMIT() asm volatile("cp.async.commit_group;")
#define CP_WAIT(n)  asm volatile("cp.async.wait_group %0;" :: "n"(n))

__device__ __forceinline__ void mma_bf16(float* c, const uint32_t* a, const uint32_t* b) {
    asm volatile(
        "mma.sync.aligned.m16n8k16.row.col.f32.bf16.bf16.f32 "
        "{%0,%1,%2,%3}, {%4,%5,%6,%7}, {%8,%9}, {%0,%1,%2,%3};"
        : "+f"(c[0]), "+f"(c[1]), "+f"(c[2]), "+f"(c[3])
        : "r"(a[0]), "r"(a[1]), "r"(a[2]), "r"(a[3]), "r"(b[0]), "r"(b[1]));
}

__device__ __forceinline__ void ldsm_x4(uint32_t* r, uint32_t addr) {
    asm volatile("ldmatrix.sync.aligned.m8n8.x4.shared.b16 {%0,%1,%2,%3}, [%4];"
                 : "=r"(r[0]), "=r"(r[1]), "=r"(r[2]), "=r"(r[3]) : "r"(addr));
}
__device__ __forceinline__ void ldsm_x4t(uint32_t* r, uint32_t addr) {
    asm volatile("ldmatrix.sync.aligned.m8n8.x4.trans.shared.b16 {%0,%1,%2,%3}, [%4];"
                 : "=r"(r[0]), "=r"(r[1]), "=r"(r[2]), "=r"(r[3]) : "r"(addr));
}

__device__ __forceinline__ uint32_t pack_bf16(float a, float b) {
    __nv_bfloat162 t = __floats2bfloat162_rn(a, b);
    return *(uint32_t*)&t;
}

__device__ __forceinline__ void split_store2(bf16* Ch, bf16* Cl, size_t off,
                                             float a, float b) {
    float ha = __bfloat162float(__float2bfloat16_rn(a));
    float hb = __bfloat162float(__float2bfloat16_rn(b));
    *(uint32_t*)(Ch + off) = pack_bf16(ha, hb);
    *(uint32_t*)(Cl + off) = pack_bf16(a - ha, b - hb);
}

// ---------------------------------------------------------------------------
// Splitter: fp32 -> (hi, lo) bf16 planes for x and all 6 weight matrices.
// ---------------------------------------------------------------------------
__global__ void __launch_bounds__(256)
split_inputs(const float* __restrict__ x,  const float* __restrict__ Wq,
             const float* __restrict__ Wk, const float* __restrict__ Wv,
             const float* __restrict__ Wo, const float* __restrict__ W1,
             const float* __restrict__ W2)
{
    const float* src; bf16 *ph, *pl; int n4;
    switch (blockIdx.y) {
        case 0: src = x;  ph = g_xh;  pl = g_xl;  n4 = MTOT * DMODEL / 4; break;
        case 1: src = Wq; ph = g_Wqh; pl = g_Wql; n4 = DMODEL * DMODEL / 4; break;
        case 2: src = Wk; ph = g_Wkh; pl = g_Wkl; n4 = DMODEL * DMODEL / 4; break;
        case 3: src = Wv; ph = g_Wvh; pl = g_Wvl; n4 = DMODEL * DMODEL / 4; break;
        case 4: src = Wo; ph = g_Woh; pl = g_Wol; n4 = DMODEL * DMODEL / 4; break;
        case 5: src = W1; ph = g_W1h; pl = g_W1l; n4 = DMODEL * DFF / 4;    break;
        default:src = W2; ph = g_W2h; pl = g_W2l; n4 = DFF * DMODEL / 4;    break;
    }
    for (int i = blockIdx.x * 256 + threadIdx.x; i < n4; i += gridDim.x * 256) {
        float4 v = ((const float4*)src)[i];
        float hx = __bfloat162float(__float2bfloat16_rn(v.x));
        float hy = __bfloat162float(__float2bfloat16_rn(v.y));
        float hz = __bfloat162float(__float2bfloat16_rn(v.z));
        float hw = __bfloat162float(__float2bfloat16_rn(v.w));
        uint2 hv, lv;
        hv.x = pack_bf16(hx, hy);             hv.y = pack_bf16(hz, hw);
        lv.x = pack_bf16(v.x - hx, v.y - hy); lv.y = pack_bf16(v.z - hz, v.w - hw);
        ((uint2*)ph)[i] = hv;
        ((uint2*)pl)[i] = lv;
    }
}

// ---------------------------------------------------------------------------
// bf16 tensor-core GEMM: 128 threads (4 warps, 2x2), tile 64x128,
// warp tile 32x64 (48 MMA per 12 LDSM per k16). 2-stage cp.async.
// 3xBF16 split (hi*hi + hi*lo + lo*hi).
// ---------------------------------------------------------------------------
#define G_APL (64 * 80)     // A plane bytes
#define G_BPL (32 * 272)    // B plane bytes
#define G_STG (2 * G_APL + 2 * G_BPL)   // 27648
#define GEMM_SMEM (2 * G_STG)           // 55296

template <int OMODE, bool RELU>
__device__ __forceinline__ void gemm64_body(
    const bf16* __restrict__ Ah, const bf16* __restrict__ Al,
    const bf16* __restrict__ Bh, const bf16* __restrict__ Bl,
    const float* __restrict__ bias,
    float* __restrict__ Cf, bf16* __restrict__ Ch, bf16* __restrict__ Cl,
    int N, int Kstride, int Kloop, float scale, int bx, int by)
{
    extern __shared__ __align__(16) char dy[];
    const int tid    = threadIdx.x;
    const int wid    = tid >> 5;
    const int lane   = tid & 31;
    const int warp_m = wid & 1;
    const int warp_n = wid >> 1;
    const int gid    = lane >> 2;
    const int tig    = lane & 3;
    const uint32_t sb = smem_u32(dy);

    float acc[2][8][4];
#pragma unroll
    for (int mt = 0; mt < 2; mt++)
#pragma unroll
        for (int nt = 0; nt < 8; nt++)
#pragma unroll
            for (int e = 0; e < 4; e++) acc[mt][nt][e] = 0.f;

    // cp.async offsets.
    // A: 64 rows x 64 B per plane = 256 cp16; 2 thr/row, each copies 32 B (2 cp16).
    const int ra = tid >> 1;
    const uint32_t aSm = sb + (uint32_t)ra * 80 + (uint32_t)((tid & 1) * 32);
    const size_t   aGm = (size_t)(by * 64 + ra) * Kstride + (tid & 1) * 16;
    // B: 32 rows x 256 B per plane = 512 cp16; 4 rows/thread (rb, rb+8, +16, +24).
    const int rb = tid >> 4, cb = tid & 15;
    const uint32_t bSm = sb + 2u * G_APL + (uint32_t)rb * 272 + (uint32_t)cb * 16;
    const size_t   bGm = (size_t)rb * N + bx * 128 + cb * 8;

    const int NKC = Kloop >> 5;

    auto issue = [&](int kc) {
        const uint32_t so = (uint32_t)(kc & 1) * G_STG;
        const bf16* ah = Ah + aGm + kc * 32;
        const bf16* al = Al + aGm + kc * 32;
        cp16(aSm + so,              ah);
        cp16(aSm + so + 16,         ah + 8);
        cp16(aSm + so + G_APL,      al);
        cp16(aSm + so + G_APL + 16, al + 8);
#pragma unroll
        for (int j = 0; j < 4; j++) {
            size_t g = bGm + (size_t)(kc * 32 + j * 8) * N;
            uint32_t s = bSm + so + (uint32_t)(j * 8) * 272;
            cp16(s,         Bh + g);
            cp16(s + G_BPL, Bl + g);
        }
        CP_COMMIT();
    };

    issue(0);

    // fragment base addresses
    const uint32_t aOff = sb + (uint32_t)(warp_m * 32 + (lane & 15)) * 80
                        + (uint32_t)((lane >> 4) * 8) * 2;
    const uint32_t bFr = sb + 2u * G_APL
                       + (uint32_t)((lane & 8) + (lane & 7)) * 272
                       + (uint32_t)(((lane & 16) >> 1) + warp_n * 64) * 2;

    for (int kc = 0; kc < NKC; kc++) {
        CP_WAIT(0);
        __syncthreads();
        if (kc + 1 < NKC) issue(kc + 1);

        const uint32_t so = (uint32_t)(kc & 1) * G_STG;
#pragma unroll
        for (int ks = 0; ks < 2; ks++) {
            uint32_t ah[2][4], al[2][4];
#pragma unroll
            for (int mt = 0; mt < 2; mt++) {
                uint32_t ao = so + (uint32_t)(mt * 16) * 80 + (uint32_t)(ks * 16) * 2;
                ldsm_x4(ah[mt], aOff + ao);
                ldsm_x4(al[mt], aOff + ao + G_APL);
            }
#pragma unroll
            for (int np = 0; np < 4; np++) {
                uint32_t bh[4], bl[4];
                uint32_t bo = so + (uint32_t)(ks * 16) * 272 + (uint32_t)(np * 16) * 2;
                ldsm_x4t(bh, bFr + bo);
                ldsm_x4t(bl, bFr + bo + G_BPL);
#pragma unroll
                for (int mt = 0; mt < 2; mt++) {
                    mma_bf16(acc[mt][2 * np],     ah[mt], bh);
                    mma_bf16(acc[mt][2 * np],     ah[mt], bl);
                    mma_bf16(acc[mt][2 * np],     al[mt], bh);
                    mma_bf16(acc[mt][2 * np + 1], ah[mt], bh + 2);
                    mma_bf16(acc[mt][2 * np + 1], ah[mt], bl + 2);
                    mma_bf16(acc[mt][2 * np + 1], al[mt], bh + 2);
                }
            }
        }
        __syncthreads();
    }

    const int m0 = by * 64 + warp_m * 32;
    const int n0 = bx * 128 + warp_n * 64;
#pragma unroll
    for (int nt = 0; nt < 8; nt++) {
        const int col = n0 + nt * 8 + tig * 2;
        const float b0 = bias ? bias[col] : 0.f;
        const float b1 = bias ? bias[col + 1] : 0.f;
#pragma unroll
        for (int mt = 0; mt < 2; mt++) {
            const int row0 = m0 + mt * 16 + gid;
            float v00 = acc[mt][nt][0] + b0, v01 = acc[mt][nt][1] + b1;
            float v10 = acc[mt][nt][2] + b0, v11 = acc[mt][nt][3] + b1;
            if (RELU) {
                v00 = fmaxf(v00, 0.f); v01 = fmaxf(v01, 0.f);
                v10 = fmaxf(v10, 0.f); v11 = fmaxf(v11, 0.f);
            }
            v00 *= scale; v01 *= scale; v10 *= scale; v11 *= scale;
            if (OMODE == 0) {
                *(float2*)(Cf + (size_t)row0 * N + col)       = make_float2(v00, v01);
                *(float2*)(Cf + (size_t)(row0 + 8) * N + col) = make_float2(v10, v11);
            } else {
                split_store2(Ch, Cl, (size_t)row0 * N + col,       v00, v01);
                split_store2(Ch, Cl, (size_t)(row0 + 8) * N + col, v10, v11);
            }
        }
    }
}

__global__ void __launch_bounds__(128, 4)
gemm_qkv_bias(const float* __restrict__ bq, const float* __restrict__ bk,
              const float* __restrict__ bv)
{
    const int z = blockIdx.z;
    const bf16 *Bh_, *Bl_; bf16 *Oh, *Ol; const float* bias; float scale;
    if (z == 0)      { Bh_ = g_Wqh; Bl_ = g_Wql; Oh = g_Qh; Ol = g_Ql; bias = bq; scale = 0.125f; }
    else if (z == 1) { Bh_ = g_Wkh; Bl_ = g_Wkl; Oh = g_Kh; Ol = g_Kl; bias = bk; scale = 1.f; }
    else             { Bh_ = g_Wvh; Bl_ = g_Wvl; Oh = g_Vh; Ol = g_Vl; bias = bv; scale = 1.f; }
    gemm64_body<1, false>(g_xh, g_xl, Bh_, Bl_, bias, nullptr, Oh, Ol,
                          DMODEL, DMODEL, DMODEL, scale, blockIdx.x, blockIdx.y);
}

template <int OMODE, bool RELU>
__global__ void __launch_bounds__(128, 4)
gemm_sp(const bf16* __restrict__ Ah, const bf16* __restrict__ Al,
        const bf16* __restrict__ Bh, const bf16* __restrict__ Bl,
        const float* __restrict__ bias,
        float* __restrict__ Cf, bf16* __restrict__ Ch, bf16* __restrict__ Cl,
        int N, int K)
{
    gemm64_body<OMODE, RELU>(Ah, Al, Bh, Bl, bias, Cf, Ch, Cl,
                             N, K, K, 1.f, blockIdx.x, blockIdx.y);
}

// Split-K: blockIdx.z = K-slice; partials -> Cf + z*(MTOT*N); bias in slice 0.
template <int NS>
__global__ void __launch_bounds__(128, 4)
gemm_splitk(const bf16* __restrict__ Ah, const bf16* __restrict__ Al,
            const bf16* __restrict__ Bh, const bf16* __restrict__ Bl,
            const float* __restrict__ bias, float* __restrict__ Cf,
            int N, int K)
{
    const int kz = blockIdx.z;
    const int Ksl = K / NS;
    gemm64_body<0, false>(Ah + kz * Ksl, Al + kz * Ksl,
                          Bh + (size_t)kz * Ksl * N, Bl + (size_t)kz * Ksl * N,
                          kz == 0 ? bias : nullptr,
                          Cf + (size_t)kz * MTOT * N, nullptr, nullptr,
                          N, K, Ksl, 1.f, blockIdx.x, blockIdx.y);
}

// ---------------------------------------------------------------------------
// Pipelined tensor-core flash attention: BQ=128 (8 warps), 3-stage KV
// cp.async pipeline, single sync/iter, no online softmax.
// ---------------------------------------------------------------------------
#define FA_ROW   144
#define FA_QPL   (128 * FA_ROW)
#define FA_KVPL  (32 * FA_ROW)
#define FA_KVST  (4 * FA_KVPL)
#define FA_BASE  (2 * FA_QPL)
#define FA_NST   3
#define FA_SMEM  (FA_BASE + FA_NST * FA_KVST)   // 92160

__global__ void __launch_bounds__(256)
flash_attn_mma()
{
    constexpr int BKV = 32, DH = HEADDIM, DM = DMODEL;
    extern __shared__ __align__(16) char dy[];

    const int tid  = threadIdx.x;
    const int wid  = tid >> 5;
    const int lane = tid & 31;
    const int g    = lane >> 2;
    const int tig  = lane & 3;
    const uint32_t sb = smem_u32(dy);

    const int bh = blockIdx.y;
    const int b  = bh >> 3;
    const int h  = bh & 7;
    const int q0 = blockIdx.x * 128;

    const size_t hoff = (size_t)b * SEQ * DM + h * DH;

    const int kvr = tid >> 3, kvc = (tid & 7);
    auto issue_kv = [&](int it) {
        const uint32_t so = FA_BASE + (uint32_t)(it % FA_NST) * FA_KVST;
        uint32_t s = sb + so + (uint32_t)kvr * FA_ROW + (uint32_t)kvc * 16;
        size_t gm = hoff + (size_t)(it * BKV + kvr) * DM + kvc * 8;
        cp16(s,               g_Kh + gm);
        cp16(s + FA_KVPL,     g_Kl + gm);
        cp16(s + 2 * FA_KVPL, g_Vh + gm);
        cp16(s + 3 * FA_KVPL, g_Vl + gm);
        CP_COMMIT();
    };

    issue_kv(0);
    issue_kv(1);

#pragma unroll
    for (int j = 0; j < 4; j++) {
        int i = j * 256 + tid;
        int r = i >> 3, c8 = (i & 7) * 8;
        size_t off = hoff + (size_t)(q0 + r) * DM + c8;
        *(uint4*)(dy + (uint32_t)r * FA_ROW + c8 * 2)          = *(const uint4*)(g_Qh + off);
        *(uint4*)(dy + FA_QPL + (uint32_t)r * FA_ROW + c8 * 2) = *(const uint4*)(g_Ql + off);
    }

    const uint32_t qRowA = (uint32_t)(wid * 16 + (lane & 8) + (lane & 7));
    const uint32_t aColO = (uint32_t)((lane & 16) >> 1);
    const uint32_t qBaseH = sb + qRowA * FA_ROW + aColO * 2;
    const uint32_t qBaseL = qBaseH + FA_QPL;
    const uint32_t kRowO = (uint32_t)(((lane & 16) >> 1) + (lane & 7));
    const uint32_t kColO = (uint32_t)(lane & 8);
    const uint32_t kBase = sb + FA_BASE + kRowO * FA_ROW + kColO * 2;
    const uint32_t vRowO = (uint32_t)((lane & 8) + (lane & 7));
    const uint32_t vColO = (uint32_t)((lane & 16) >> 1);
    const uint32_t vBase = sb + FA_BASE + 2 * FA_KVPL + vRowO * FA_ROW + vColO * 2;

    float l_t = 0.f, l_b = 0.f;
    float O[8][4];
#pragma unroll
    for (int dt = 0; dt < 8; dt++)
#pragma unroll
        for (int e = 0; e < 4; e++) O[dt][e] = 0.f;

    constexpr int NIT = SEQ / BKV;   // 64
    for (int it = 0; it < NIT; it++) {
        CP_WAIT(1);
        __syncthreads();
        if (it + 2 < NIT) issue_kv(it + 2); else CP_COMMIT();

        const uint32_t so = (uint32_t)(it % FA_NST) * FA_KVST;

        float S[4][4];
#pragma unroll
        for (int t = 0; t < 4; t++)
#pragma unroll
            for (int e = 0; e < 4; e++) S[t][e] = 0.f;

#pragma unroll
        for (int ks = 0; ks < 4; ks++) {
            uint32_t qh[4], ql[4];
            ldsm_x4(qh, qBaseH + (uint32_t)(ks * 16) * 2);
            ldsm_x4(ql, qBaseL + (uint32_t)(ks * 16) * 2);
#pragma unroll
            for (int np = 0; np < 2; np++) {
                uint32_t kbh[4], kbl[4];
                uint32_t ro = so + (uint32_t)(np * 16) * FA_ROW + (uint32_t)(ks * 16) * 2;
                ldsm_x4(kbh, kBase + ro);
                ldsm_x4(kbl, kBase + ro + FA_KVPL);
                mma_bf16(S[2 * np],     qh, kbh);
                mma_bf16(S[2 * np],     qh, kbl);
                mma_bf16(S[2 * np],     ql, kbh);
                mma_bf16(S[2 * np + 1], qh, kbh + 2);
                mma_bf16(S[2 * np + 1], qh, kbl + 2);
                mma_bf16(S[2 * np + 1], ql, kbh + 2);
            }
        }

#pragma unroll
        for (int t = 0; t < 4; t++) {
            S[t][0] = __expf(S[t][0]);
            S[t][1] = __expf(S[t][1]);
            S[t][2] = __expf(S[t][2]);
            S[t][3] = __expf(S[t][3]);
            l_t += S[t][0] + S[t][1];
            l_b += S[t][2] + S[t][3];
        }

#pragma unroll
        for (int ks = 0; ks < 2; ks++) {
            uint32_t Ph[4], Pl[4];
#pragma unroll
            for (int half = 0; half < 2; half++) {
                const int t = 2 * ks + half;
                float h0 = __bfloat162float(__float2bfloat16_rn(S[t][0]));
                float h1 = __bfloat162float(__float2bfloat16_rn(S[t][1]));
                float h2 = __bfloat162float(__float2bfloat16_rn(S[t][2]));
                float h3 = __bfloat162float(__float2bfloat16_rn(S[t][3]));
                Ph[2 * half + 0] = pack_bf16(h0, h1);
                Ph[2 * half + 1] = pack_bf16(h2, h3);
                Pl[2 * half + 0] = pack_bf16(S[t][0] - h0, S[t][1] - h1);
                Pl[2 * half + 1] = pack_bf16(S[t][2] - h2, S[t][3] - h3);
            }
#pragma unroll
            for (int dp = 0; dp < 4; dp++) {
                uint32_t vbh[4], vbl[4];
                uint32_t off = so + (uint32_t)(ks * 16) * FA_ROW + (uint32_t)(dp * 16) * 2;
                ldsm_x4t(vbh, vBase + off);
                ldsm_x4t(vbl, vBase + off + FA_KVPL);
                mma_bf16(O[2 * dp],     Ph, vbh);
                mma_bf16(O[2 * dp],     Ph, vbl);
                mma_bf16(O[2 * dp],     Pl, vbh);
                mma_bf16(O[2 * dp + 1], Ph, vbh + 2);
                mma_bf16(O[2 * dp + 1], Ph, vbl + 2);
                mma_bf16(O[2 * dp + 1], Pl, vbh + 2);
            }
        }
    }

    l_t += __shfl_xor_sync(0xffffffffu, l_t, 1);
    l_t += __shfl_xor_sync(0xffffffffu, l_t, 2);
    l_b += __shfl_xor_sync(0xffffffffu, l_b, 1);
    l_b += __shfl_xor_sync(0xffffffffu, l_b, 2);
    const float inv_t = 1.f / l_t;
    const float inv_b = 1.f / l_b;
    const int row_t = b * SEQ + q0 + wid * 16 + g;
#pragma unroll
    for (int dt = 0; dt < 8; dt++) {
        const int col = h * DH + dt * 8 + tig * 2;
        split_store2(g_Ch, g_Cl, (size_t)row_t * DM + col,
                     O[dt][0] * inv_t, O[dt][1] * inv_t);
        split_store2(g_Ch, g_Cl, (size_t)(row_t + 8) * DM + col,
                     O[dt][2] * inv_b, O[dt][3] * inv_b);
    }
}

// ---------------------------------------------------------------------------
// Fused (residual + NB split-K partials) add + LayerNorm over D=512.
// ---------------------------------------------------------------------------
template <int NB, bool SPLITOUT>
__global__ void __launch_bounds__(256)
add_ln(const float* __restrict__ A, const float* __restrict__ PS,
       const float* __restrict__ g, const float* __restrict__ be,
       float* __restrict__ out, bf16* __restrict__ oh, bf16* __restrict__ ol)
{
    __shared__ float sh[16];
    const int row = blockIdx.x;
    const int t   = threadIdx.x;
    const size_t base = (size_t)row * DMODEL;

    float v0 = A[base + t];
    float v1 = A[base + t + 256];
#pragma unroll
    for (int s = 0; s < NB; s++) {
        v0 += PS[(size_t)s * MTOT * DMODEL + base + t];
        v1 += PS[(size_t)s * MTOT * DMODEL + base + t + 256];
    }
    float s = v0 + v1;
    float q = v0 * v0 + v1 * v1;
#pragma unroll
    for (int ofs = 16; ofs; ofs >>= 1) {
        s += __shfl_xor_sync(0xffffffffu, s, ofs);
        q += __shfl_xor_sync(0xffffffffu, q, ofs);
    }
    if ((t & 31) == 0) { sh[t >> 5] = s; sh[8 + (t >> 5)] = q; }
    __syncthreads();
    if (t < 32) {
        s = (t < 8) ? sh[t]     : 0.f;
        q = (t < 8) ? sh[8 + t] : 0.f;
#pragma unroll
        for (int ofs = 4; ofs; ofs >>= 1) {
            s += __shfl_xor_sync(0xffffffffu, s, ofs);
            q += __shfl_xor_sync(0xffffffffu, q, ofs);
        }
        if (t == 0) {
            float mean = s * (1.f / DMODEL);
            float var  = q * (1.f / DMODEL) - mean * mean;
            sh[0] = mean;
            sh[1] = rsqrtf(var + LN_EPS);
        }
    }
    __syncthreads();
    float mean = sh[0], rstd = sh[1];
    float y0 = (v0 - mean) * rstd * g[t]       + be[t];
    float y1 = (v1 - mean) * rstd * g[t + 256] + be[t + 256];
    out[base + t]       = y0;
    out[base + t + 256] = y1;
    if (SPLITOUT) {
        float h0 = __bfloat162float(__float2bfloat16_rn(y0));
        float h1 = __bfloat162float(__float2bfloat16_rn(y1));
        oh[base + t]       = __float2bfloat16_rn(y0);
        ol[base + t]       = __float2bfloat16_rn(y0 - h0);
        oh[base + t + 256] = __float2bfloat16_rn(y1);
        ol[base + t + 256] = __float2bfloat16_rn(y1 - h1);
    }
}

// ---------------------------------------------------------------------------
// kernel_launch
// Inputs: x Wq bq Wk bk Wv bv Wo bo W1 b1 W2 b2 g1 be1 g2 be2
// ---------------------------------------------------------------------------
extern "C" void kernel_launch(void* const* d_in, const int* in_sizes, int n_in,
                              void* d_out, int out_size)
{
    const float* x   = (const float*)d_in[0];
    const float* Wq  = (const float*)d_in[1];
    const float* bq  = (const float*)d_in[2];
    const float* Wk  = (const float*)d_in[3];
    const float* bk  = (const float*)d_in[4];
    const float* Wv  = (const float*)d_in[5];
    const float* bv  = (const float*)d_in[6];
    const float* Wo  = (const float*)d_in[7];
    const float* bo  = (const float*)d_in[8];
    const float* W1  = (const float*)d_in[9];
    const float* b1  = (const float*)d_in[10];
    const float* W2  = (const float*)d_in[11];
    const float* b2  = (const float*)d_in[12];
    const float* g1  = (const float*)d_in[13];
    const float* be1 = (const float*)d_in[14];
    const float* g2  = (const float*)d_in[15];
    const float* be2 = (const float*)d_in[16];
    float* out = (float*)d_out;

    float *PS, *H;
    bf16 *Ch, *Cl, *Hh, *Hl, *Fh, *Fl;
    bf16 *Woh, *Wol, *W1h, *W1l, *W2h, *W2l;
    cudaGetSymbolAddress((void**)&PS,  g_PS);
    cudaGetSymbolAddress((void**)&H,   g_H);
    cudaGetSymbolAddress((void**)&Ch,  g_Ch);
    cudaGetSymbolAddress((void**)&Cl,  g_Cl);
    cudaGetSymbolAddress((void**)&Hh,  g_Hh);
    cudaGetSymbolAddress((void**)&Hl,  g_Hl);
    cudaGetSymbolAddress((void**)&Fh,  g_Fh);
    cudaGetSymbolAddress((void**)&Fl,  g_Fl);
    cudaGetSymbolAddress((void**)&Woh, g_Woh);
    cudaGetSymbolAddress((void**)&Wol, g_Wol);
    cudaGetSymbolAddress((void**)&W1h, g_W1h);
    cudaGetSymbolAddress((void**)&W1l, g_W1l);
    cudaGetSymbolAddress((void**)&W2h, g_W2h);
    cudaGetSymbolAddress((void**)&W2l, g_W2l);

    static bool attr_done = false;
    if (!attr_done) {
        cudaFuncSetAttribute(gemm_qkv_bias,
                             cudaFuncAttributeMaxDynamicSharedMemorySize, GEMM_SMEM);
        cudaFuncSetAttribute(gemm_sp<1, true>,
                             cudaFuncAttributeMaxDynamicSharedMemorySize, GEMM_SMEM);
        cudaFuncSetAttribute(gemm_splitk<2>,
                             cudaFuncAttributeMaxDynamicSharedMemorySize, GEMM_SMEM);
        cudaFuncSetAttribute(gemm_splitk<4>,
                             cudaFuncAttributeMaxDynamicSharedMemorySize, GEMM_SMEM);
        cudaFuncSetAttribute(flash_attn_mma,
                             cudaFuncAttributeMaxDynamicSharedMemorySize, FA_SMEM);
        attr_done = true;
    }

    dim3 gqkv (DMODEL / 128, MTOT / 64, 3);   // 768 CTAs
    dim3 gwo  (DMODEL / 128, MTOT / 64, 2);   // 512 CTAs
    dim3 gff1 (DFF    / 128, MTOT / 64);      // 1024 CTAs
    dim3 gw2  (DMODEL / 128, MTOT / 64, 4);   // 1024 CTAs

    // 0) split x + weights into bf16 hi/lo planes
    split_inputs<<<dim3(512, 7), 256>>>(x, Wq, Wk, Wv, Wo, W1, W2);

    // 1) QKV projections (Q pre-scaled by 1/8)
    gemm_qkv_bias<<<gqkv, 128, GEMM_SMEM>>>(bq, bk, bv);

    // 2) attention -> CTX planes
    flash_attn_mma<<<dim3(SEQ / 128, BATCH * NHEADS), 256, FA_SMEM>>>();

    // 3) output projection (split-K=2) -> PS[0..1]
    gemm_splitk<2><<<gwo, 128, GEMM_SMEM>>>(Ch, Cl, Woh, Wol, bo, PS,
                                            DMODEL, DMODEL);

    // 4) residual + 2 partials + LN1 -> H fp32 + planes
    add_ln<2, true><<<MTOT, 256>>>(x, PS, g1, be1, H, Hh, Hl);

    // 5) FFN up + ReLU -> FF planes
    gemm_sp<1, true><<<gff1, 128, GEMM_SMEM>>>(Hh, Hl, W1h, W1l, b1,
                                               nullptr, Fh, Fl, DFF, DMODEL);

    // 6) FFN down (split-K=4) -> PS[0..3]
    gemm_splitk<4><<<gw2, 128, GEMM_SMEM>>>(Fh, Fl, W2h, W2l, b2, PS,
                                            DMODEL, DFF);

    // 7) residual + 4 partials + LN2 -> out
    add_ln<4, false><<<MTOT, 256>>>(H, PS, g2, be2, out, nullptr, nullptr);
}

// round 10
// speedup vs baseline: 1.0872x; 1.0038x over previous
#include <cuda_runtime.h>
#include <cuda_bf16.h>
#include <math.h>
#include <stdint.h>

// ---------------------------------------------------------------------------
// Problem constants
// ---------------------------------------------------------------------------
#define BATCH   2
#define SEQ     2048
#define DMODEL  512
#define NHEADS  8
#define HEADDIM 64
#define DFF     2048
#define MTOT    (BATCH * SEQ)          // 4096 rows
#define LN_EPS  1e-5f

typedef __nv_bfloat16 bf16;

// ---------------------------------------------------------------------------
// Scratch (static device globals; no allocations allowed)
// ---------------------------------------------------------------------------
__device__ __align__(16) bf16 g_xh [MTOT * DMODEL], g_xl [MTOT * DMODEL];
__device__ __align__(16) bf16 g_Wqh[DMODEL * DMODEL], g_Wql[DMODEL * DMODEL];
__device__ __align__(16) bf16 g_Wkh[DMODEL * DMODEL], g_Wkl[DMODEL * DMODEL];
__device__ __align__(16) bf16 g_Wvh[DMODEL * DMODEL], g_Wvl[DMODEL * DMODEL];
__device__ __align__(16) bf16 g_Woh[DMODEL * DMODEL], g_Wol[DMODEL * DMODEL];
__device__ __align__(16) bf16 g_W1h[DMODEL * DFF],    g_W1l[DMODEL * DFF];
__device__ __align__(16) bf16 g_W2h[DFF * DMODEL],    g_W2l[DFF * DMODEL];
__device__ __align__(16) bf16 g_Qh [MTOT * DMODEL], g_Ql [MTOT * DMODEL];
__device__ __align__(16) bf16 g_Kh [MTOT * DMODEL], g_Kl [MTOT * DMODEL];
__device__ __align__(16) bf16 g_Vh [MTOT * DMODEL], g_Vl [MTOT * DMODEL];
__device__ __align__(16) bf16 g_Ch [MTOT * DMODEL], g_Cl [MTOT * DMODEL];
__device__ __align__(16) bf16 g_Hh [MTOT * DMODEL], g_Hl [MTOT * DMODEL];
__device__ __align__(16) bf16 g_Fh [MTOT * DFF],    g_Fl [MTOT * DFF];
__device__ float g_PS[4 * MTOT * DMODEL];   // split-K partial sums
__device__ float g_H [MTOT * DMODEL];

// ---------------------------------------------------------------------------
// Helpers
// ---------------------------------------------------------------------------
__device__ __forceinline__ uint32_t smem_u32(const void* p) {
    uint32_t a;
    asm("{ .reg .u64 t; cvta.to.shared.u64 t, %1; cvt.u32.u64 %0, t; }"
        : "=r"(a) : "l"(p));
    return a;
}

__device__ __forceinline__ void cp16(uint32_t s, const void* g) {
    asm volatile("cp.async.cg.shared.global [%0], [%1], 16;" :: "r"(s), "l"(g));
}
#define CP_COMMIT() asm volatile("cp.async.commit_group;")
#define CP_WAIT(n)  asm volatile("cp.async.wait_group %0;" :: "n"(n))

__device__ __forceinline__ void mma_bf16(float* c, const uint32_t* a, const uint32_t* b) {
    asm volatile(
        "mma.sync.aligned.m16n8k16.row.col.f32.bf16.bf16.f32 "
        "{%0,%1,%2,%3}, {%4,%5,%6,%7}, {%8,%9}, {%0,%1,%2,%3};"
        : "+f"(c[0]), "+f"(c[1]), "+f"(c[2]), "+f"(c[3])
        : "r"(a[0]), "r"(a[1]), "r"(a[2]), "r"(a[3]), "r"(b[0]), "r"(b[1]));
}

__device__ __forceinline__ void ldsm_x4(uint32_t* r, uint32_t addr) {
    asm volatile("ldmatrix.sync.aligned.m8n8.x4.shared.b16 {%0,%1,%2,%3}, [%4];"
                 : "=r"(r[0]), "=r"(r[1]), "=r"(r[2]), "=r"(r[3]) : "r"(addr));
}
__device__ __forceinline__ void ldsm_x4t(uint32_t* r, uint32_t addr) {
    asm volatile("ldmatrix.sync.aligned.m8n8.x4.trans.shared.b16 {%0,%1,%2,%3}, [%4];"
                 : "=r"(r[0]), "=r"(r[1]), "=r"(r[2]), "=r"(r[3]) : "r"(addr));
}

__device__ __forceinline__ uint32_t pack_bf16(float a, float b) {
    __nv_bfloat162 t = __floats2bfloat162_rn(a, b);
    return *(uint32_t*)&t;
}

__device__ __forceinline__ void split_store2(bf16* Ch, bf16* Cl, size_t off,
                                             float a, float b) {
    float ha = __bfloat162float(__float2bfloat16_rn(a));
    float hb = __bfloat162float(__float2bfloat16_rn(b));
    *(uint32_t*)(Ch + off) = pack_bf16(ha, hb);
    *(uint32_t*)(Cl + off) = pack_bf16(a - ha, b - hb);
}

// ---------------------------------------------------------------------------
// Splitter: fp32 -> (hi, lo) bf16 planes for x and all 6 weight matrices.
// ---------------------------------------------------------------------------
__global__ void __launch_bounds__(256)
split_inputs(const float* __restrict__ x,  const float* __restrict__ Wq,
             const float* __restrict__ Wk, const float* __restrict__ Wv,
             const float* __restrict__ Wo, const float* __restrict__ W1,
             const float* __restrict__ W2)
{
    const float* src; bf16 *ph, *pl; int n4;
    switch (blockIdx.y) {
        case 0: src = x;  ph = g_xh;  pl = g_xl;  n4 = MTOT * DMODEL / 4; break;
        case 1: src = Wq; ph = g_Wqh; pl = g_Wql; n4 = DMODEL * DMODEL / 4; break;
        case 2: src = Wk; ph = g_Wkh; pl = g_Wkl; n4 = DMODEL * DMODEL / 4; break;
        case 3: src = Wv; ph = g_Wvh; pl = g_Wvl; n4 = DMODEL * DMODEL / 4; break;
        case 4: src = Wo; ph = g_Woh; pl = g_Wol; n4 = DMODEL * DMODEL / 4; break;
        case 5: src = W1; ph = g_W1h; pl = g_W1l; n4 = DMODEL * DFF / 4;    break;
        default:src = W2; ph = g_W2h; pl = g_W2l; n4 = DFF * DMODEL / 4;    break;
    }
    for (int i = blockIdx.x * 256 + threadIdx.x; i < n4; i += gridDim.x * 256) {
        float4 v = ((const float4*)src)[i];
        float hx = __bfloat162float(__float2bfloat16_rn(v.x));
        float hy = __bfloat162float(__float2bfloat16_rn(v.y));
        float hz = __bfloat162float(__float2bfloat16_rn(v.z));
        float hw = __bfloat162float(__float2bfloat16_rn(v.w));
        uint2 hv, lv;
        hv.x = pack_bf16(hx, hy);             hv.y = pack_bf16(hz, hw);
        lv.x = pack_bf16(v.x - hx, v.y - hy); lv.y = pack_bf16(v.z - hz, v.w - hw);
        ((uint2*)ph)[i] = hv;
        ((uint2*)pl)[i] = lv;
    }
}

// ---------------------------------------------------------------------------
// bf16 tensor-core GEMM: 128 threads (4 warps, 2x2), tile 64x128,
// warp tile 32x64 (48 MMA per 12 LDSM per k16). 2-stage cp.async.
// 3xBF16 split (hi*hi + hi*lo + lo*hi).
// ---------------------------------------------------------------------------
#define G_APL (64 * 80)     // A plane bytes
#define G_BPL (32 * 272)    // B plane bytes
#define G_STG (2 * G_APL + 2 * G_BPL)   // 27648
#define GEMM_SMEM (2 * G_STG)           // 55296

template <int OMODE, bool RELU>
__device__ __forceinline__ void gemm64_body(
    const bf16* __restrict__ Ah, const bf16* __restrict__ Al,
    const bf16* __restrict__ Bh, const bf16* __restrict__ Bl,
    const float* __restrict__ bias,
    float* __restrict__ Cf, bf16* __restrict__ Ch, bf16* __restrict__ Cl,
    int N, int Kstride, int Kloop, float scale, int bx, int by)
{
    extern __shared__ __align__(16) char dy[];
    const int tid    = threadIdx.x;
    const int wid    = tid >> 5;
    const int lane   = tid & 31;
    const int warp_m = wid & 1;
    const int warp_n = wid >> 1;
    const int gid    = lane >> 2;
    const int tig    = lane & 3;
    const uint32_t sb = smem_u32(dy);

    float acc[2][8][4];
#pragma unroll
    for (int mt = 0; mt < 2; mt++)
#pragma unroll
        for (int nt = 0; nt < 8; nt++)
#pragma unroll
            for (int e = 0; e < 4; e++) acc[mt][nt][e] = 0.f;

    // cp.async offsets.
    // A: 64 rows x 64 B per plane = 256 cp16; 2 thr/row, each copies 32 B (2 cp16).
    const int ra = tid >> 1;
    const uint32_t aSm = sb + (uint32_t)ra * 80 + (uint32_t)((tid & 1) * 32);
    const size_t   aGm = (size_t)(by * 64 + ra) * Kstride + (tid & 1) * 16;
    // B: 32 rows x 256 B per plane = 512 cp16; 4 rows/thread (rb, rb+8, +16, +24).
    const int rb = tid >> 4, cb = tid & 15;
    const uint32_t bSm = sb + 2u * G_APL + (uint32_t)rb * 272 + (uint32_t)cb * 16;
    const size_t   bGm = (size_t)rb * N + bx * 128 + cb * 8;

    const int NKC = Kloop >> 5;

    auto issue = [&](int kc) {
        const uint32_t so = (uint32_t)(kc & 1) * G_STG;
        const bf16* ah = Ah + aGm + kc * 32;
        const bf16* al = Al + aGm + kc * 32;
        cp16(aSm + so,              ah);
        cp16(aSm + so + 16,         ah + 8);
        cp16(aSm + so + G_APL,      al);
        cp16(aSm + so + G_APL + 16, al + 8);
#pragma unroll
        for (int j = 0; j < 4; j++) {
            size_t g = bGm + (size_t)(kc * 32 + j * 8) * N;
            uint32_t s = bSm + so + (uint32_t)(j * 8) * 272;
            cp16(s,         Bh + g);
            cp16(s + G_BPL, Bl + g);
        }
        CP_COMMIT();
    };

    issue(0);

    // fragment base addresses
    const uint32_t aOff = sb + (uint32_t)(warp_m * 32 + (lane & 15)) * 80
                        + (uint32_t)((lane >> 4) * 8) * 2;
    const uint32_t bFr = sb + 2u * G_APL
                       + (uint32_t)((lane & 8) + (lane & 7)) * 272
                       + (uint32_t)(((lane & 16) >> 1) + warp_n * 64) * 2;

    for (int kc = 0; kc < NKC; kc++) {
        CP_WAIT(0);
        __syncthreads();
        if (kc + 1 < NKC) issue(kc + 1);

        const uint32_t so = (uint32_t)(kc & 1) * G_STG;
#pragma unroll
        for (int ks = 0; ks < 2; ks++) {
            uint32_t ah[2][4], al[2][4];
#pragma unroll
            for (int mt = 0; mt < 2; mt++) {
                uint32_t ao = so + (uint32_t)(mt * 16) * 80 + (uint32_t)(ks * 16) * 2;
                ldsm_x4(ah[mt], aOff + ao);
                ldsm_x4(al[mt], aOff + ao + G_APL);
            }
#pragma unroll
            for (int np = 0; np < 4; np++) {
                uint32_t bh[4], bl[4];
                uint32_t bo = so + (uint32_t)(ks * 16) * 272 + (uint32_t)(np * 16) * 2;
                ldsm_x4t(bh, bFr + bo);
                ldsm_x4t(bl, bFr + bo + G_BPL);
#pragma unroll
                for (int mt = 0; mt < 2; mt++) {
                    mma_bf16(acc[mt][2 * np],     ah[mt], bh);
                    mma_bf16(acc[mt][2 * np],     ah[mt], bl);
                    mma_bf16(acc[mt][2 * np],     al[mt], bh);
                    mma_bf16(acc[mt][2 * np + 1], ah[mt], bh + 2);
                    mma_bf16(acc[mt][2 * np + 1], ah[mt], bl + 2);
                    mma_bf16(acc[mt][2 * np + 1], al[mt], bh + 2);
                }
            }
        }
        __syncthreads();
    }

    const int m0 = by * 64 + warp_m * 32;
    const int n0 = bx * 128 + warp_n * 64;
#pragma unroll
    for (int nt = 0; nt < 8; nt++) {
        const int col = n0 + nt * 8 + tig * 2;
        const float b0 = bias ? bias[col] : 0.f;
        const float b1 = bias ? bias[col + 1] : 0.f;
#pragma unroll
        for (int mt = 0; mt < 2; mt++) {
            const int row0 = m0 + mt * 16 + gid;
            float v00 = acc[mt][nt][0] + b0, v01 = acc[mt][nt][1] + b1;
            float v10 = acc[mt][nt][2] + b0, v11 = acc[mt][nt][3] + b1;
            if (RELU) {
                v00 = fmaxf(v00, 0.f); v01 = fmaxf(v01, 0.f);
                v10 = fmaxf(v10, 0.f); v11 = fmaxf(v11, 0.f);
            }
            v00 *= scale; v01 *= scale; v10 *= scale; v11 *= scale;
            if (OMODE == 0) {
                *(float2*)(Cf + (size_t)row0 * N + col)       = make_float2(v00, v01);
                *(float2*)(Cf + (size_t)(row0 + 8) * N + col) = make_float2(v10, v11);
            } else {
                split_store2(Ch, Cl, (size_t)row0 * N + col,       v00, v01);
                split_store2(Ch, Cl, (size_t)(row0 + 8) * N + col, v10, v11);
            }
        }
    }
}

__global__ void __launch_bounds__(128, 4)
gemm_qkv_bias(const float* __restrict__ bq, const float* __restrict__ bk,
              const float* __restrict__ bv)
{
    const int z = blockIdx.z;
    const bf16 *Bh_, *Bl_; bf16 *Oh, *Ol; const float* bias; float scale;
    if (z == 0)      { Bh_ = g_Wqh; Bl_ = g_Wql; Oh = g_Qh; Ol = g_Ql; bias = bq; scale = 0.125f; }
    else if (z == 1) { Bh_ = g_Wkh; Bl_ = g_Wkl; Oh = g_Kh; Ol = g_Kl; bias = bk; scale = 1.f; }
    else             { Bh_ = g_Wvh; Bl_ = g_Wvl; Oh = g_Vh; Ol = g_Vl; bias = bv; scale = 1.f; }
    gemm64_body<1, false>(g_xh, g_xl, Bh_, Bl_, bias, nullptr, Oh, Ol,
                          DMODEL, DMODEL, DMODEL, scale, blockIdx.x, blockIdx.y);
}

template <int OMODE, bool RELU>
__global__ void __launch_bounds__(128, 4)
gemm_sp(const bf16* __restrict__ Ah, const bf16* __restrict__ Al,
        const bf16* __restrict__ Bh, const bf16* __restrict__ Bl,
        const float* __restrict__ bias,
        float* __restrict__ Cf, bf16* __restrict__ Ch, bf16* __restrict__ Cl,
        int N, int K)
{
    gemm64_body<OMODE, RELU>(Ah, Al, Bh, Bl, bias, Cf, Ch, Cl,
                             N, K, K, 1.f, blockIdx.x, blockIdx.y);
}

// Split-K: blockIdx.z = K-slice; partials -> Cf + z*(MTOT*N); bias in slice 0.
template <int NS>
__global__ void __launch_bounds__(128, 4)
gemm_splitk(const bf16* __restrict__ Ah, const bf16* __restrict__ Al,
            const bf16* __restrict__ Bh, const bf16* __restrict__ Bl,
            const float* __restrict__ bias, float* __restrict__ Cf,
            int N, int K)
{
    const int kz = blockIdx.z;
    const int Ksl = K / NS;
    gemm64_body<0, false>(Ah + kz * Ksl, Al + kz * Ksl,
                          Bh + (size_t)kz * Ksl * N, Bl + (size_t)kz * Ksl * N,
                          kz == 0 ? bias : nullptr,
                          Cf + (size_t)kz * MTOT * N, nullptr, nullptr,
                          N, K, Ksl, 1.f, blockIdx.x, blockIdx.y);
}

// ---------------------------------------------------------------------------
// Pipelined tensor-core flash attention: BQ=128 (8 warps), 3-stage KV
// cp.async pipeline, single sync/iter, no online softmax.
// __launch_bounds__(256, 2): force regs <= 128 so 2 CTAs/SM are resident
// (smem 2 x 92160 = 184320 <= 228 KB).
// ---------------------------------------------------------------------------
#define FA_ROW   144
#define FA_QPL   (128 * FA_ROW)
#define FA_KVPL  (32 * FA_ROW)
#define FA_KVST  (4 * FA_KVPL)
#define FA_BASE  (2 * FA_QPL)
#define FA_NST   3
#define FA_SMEM  (FA_BASE + FA_NST * FA_KVST)   // 92160

__global__ void __launch_bounds__(256, 2)
flash_attn_mma()
{
    constexpr int BKV = 32, DH = HEADDIM, DM = DMODEL;
    extern __shared__ __align__(16) char dy[];

    const int tid  = threadIdx.x;
    const int wid  = tid >> 5;
    const int lane = tid & 31;
    const int g    = lane >> 2;
    const int tig  = lane & 3;
    const uint32_t sb = smem_u32(dy);

    const int bh = blockIdx.y;
    const int b  = bh >> 3;
    const int h  = bh & 7;
    const int q0 = blockIdx.x * 128;

    const size_t hoff = (size_t)b * SEQ * DM + h * DH;

    const int kvr = tid >> 3, kvc = (tid & 7);
    auto issue_kv = [&](int it) {
        const uint32_t so = FA_BASE + (uint32_t)(it % FA_NST) * FA_KVST;
        uint32_t s = sb + so + (uint32_t)kvr * FA_ROW + (uint32_t)kvc * 16;
        size_t gm = hoff + (size_t)(it * BKV + kvr) * DM + kvc * 8;
        cp16(s,               g_Kh + gm);
        cp16(s + FA_KVPL,     g_Kl + gm);
        cp16(s + 2 * FA_KVPL, g_Vh + gm);
        cp16(s + 3 * FA_KVPL, g_Vl + gm);
        CP_COMMIT();
    };

    issue_kv(0);
    issue_kv(1);

#pragma unroll
    for (int j = 0; j < 4; j++) {
        int i = j * 256 + tid;
        int r = i >> 3, c8 = (i & 7) * 8;
        size_t off = hoff + (size_t)(q0 + r) * DM + c8;
        *(uint4*)(dy + (uint32_t)r * FA_ROW + c8 * 2)          = *(const uint4*)(g_Qh + off);
        *(uint4*)(dy + FA_QPL + (uint32_t)r * FA_ROW + c8 * 2) = *(const uint4*)(g_Ql + off);
    }

    const uint32_t qRowA = (uint32_t)(wid * 16 + (lane & 8) + (lane & 7));
    const uint32_t aColO = (uint32_t)((lane & 16) >> 1);
    const uint32_t qBaseH = sb + qRowA * FA_ROW + aColO * 2;
    const uint32_t qBaseL = qBaseH + FA_QPL;
    const uint32_t kRowO = (uint32_t)(((lane & 16) >> 1) + (lane & 7));
    const uint32_t kColO = (uint32_t)(lane & 8);
    const uint32_t kBase = sb + FA_BASE + kRowO * FA_ROW + kColO * 2;
    const uint32_t vRowO = (uint32_t)((lane & 8) + (lane & 7));
    const uint32_t vColO = (uint32_t)((lane & 16) >> 1);
    const uint32_t vBase = sb + FA_BASE + 2 * FA_KVPL + vRowO * FA_ROW + vColO * 2;

    float l_t = 0.f, l_b = 0.f;
    float O[8][4];
#pragma unroll
    for (int dt = 0; dt < 8; dt++)
#pragma unroll
        for (int e = 0; e < 4; e++) O[dt][e] = 0.f;

    constexpr int NIT = SEQ / BKV;   // 64
    for (int it = 0; it < NIT; it++) {
        CP_WAIT(1);
        __syncthreads();
        if (it + 2 < NIT) issue_kv(it + 2); else CP_COMMIT();

        const uint32_t so = (uint32_t)(it % FA_NST) * FA_KVST;

        float S[4][4];
#pragma unroll
        for (int t = 0; t < 4; t++)
#pragma unroll
            for (int e = 0; e < 4; e++) S[t][e] = 0.f;

#pragma unroll
        for (int ks = 0; ks < 4; ks++) {
            uint32_t qh[4], ql[4];
            ldsm_x4(qh, qBaseH + (uint32_t)(ks * 16) * 2);
            ldsm_x4(ql, qBaseL + (uint32_t)(ks * 16) * 2);
#pragma unroll
            for (int np = 0; np < 2; np++) {
                uint32_t kbh[4], kbl[4];
                uint32_t ro = so + (uint32_t)(np * 16) * FA_ROW + (uint32_t)(ks * 16) * 2;
                ldsm_x4(kbh, kBase + ro);
                ldsm_x4(kbl, kBase + ro + FA_KVPL);
                mma_bf16(S[2 * np],     qh, kbh);
                mma_bf16(S[2 * np],     qh, kbl);
                mma_bf16(S[2 * np],     ql, kbh);
                mma_bf16(S[2 * np + 1], qh, kbh + 2);
                mma_bf16(S[2 * np + 1], qh, kbl + 2);
                mma_bf16(S[2 * np + 1], ql, kbh + 2);
            }
        }

#pragma unroll
        for (int t = 0; t < 4; t++) {
            S[t][0] = __expf(S[t][0]);
            S[t][1] = __expf(S[t][1]);
            S[t][2] = __expf(S[t][2]);
            S[t][3] = __expf(S[t][3]);
            l_t += S[t][0] + S[t][1];
            l_b += S[t][2] + S[t][3];
        }

#pragma unroll
        for (int ks = 0; ks < 2; ks++) {
            uint32_t Ph[4], Pl[4];
#pragma unroll
            for (int half = 0; half < 2; half++) {
                const int t = 2 * ks + half;
                float h0 = __bfloat162float(__float2bfloat16_rn(S[t][0]));
                float h1 = __bfloat162float(__float2bfloat16_rn(S[t][1]));
                float h2 = __bfloat162float(__float2bfloat16_rn(S[t][2]));
                float h3 = __bfloat162float(__float2bfloat16_rn(S[t][3]));
                Ph[2 * half + 0] = pack_bf16(h0, h1);
                Ph[2 * half + 1] = pack_bf16(h2, h3);
                Pl[2 * half + 0] = pack_bf16(S[t][0] - h0, S[t][1] - h1);
                Pl[2 * half + 1] = pack_bf16(S[t][2] - h2, S[t][3] - h3);
            }
#pragma unroll
            for (int dp = 0; dp < 4; dp++) {
                uint32_t vbh[4], vbl[4];
                uint32_t off = so + (uint32_t)(ks * 16) * FA_ROW + (uint32_t)(dp * 16) * 2;
                ldsm_x4t(vbh, vBase + off);
                ldsm_x4t(vbl, vBase + off + FA_KVPL);
                mma_bf16(O[2 * dp],     Ph, vbh);
                mma_bf16(O[2 * dp],     Ph, vbl);
                mma_bf16(O[2 * dp],     Pl, vbh);
                mma_bf16(O[2 * dp + 1], Ph, vbh + 2);
                mma_bf16(O[2 * dp + 1], Ph, vbl + 2);
                mma_bf16(O[2 * dp + 1], Pl, vbh + 2);
            }
        }
    }

    l_t += __shfl_xor_sync(0xffffffffu, l_t, 1);
    l_t += __shfl_xor_sync(0xffffffffu, l_t, 2);
    l_b += __shfl_xor_sync(0xffffffffu, l_b, 1);
    l_b += __shfl_xor_sync(0xffffffffu, l_b, 2);
    const float inv_t = 1.f / l_t;
    const float inv_b = 1.f / l_b;
    const int row_t = b * SEQ + q0 + wid * 16 + g;
#pragma unroll
    for (int dt = 0; dt < 8; dt++) {
        const int col = h * DH + dt * 8 + tig * 2;
        split_store2(g_Ch, g_Cl, (size_t)row_t * DM + col,
                     O[dt][0] * inv_t, O[dt][1] * inv_t);
        split_store2(g_Ch, g_Cl, (size_t)(row_t + 8) * DM + col,
                     O[dt][2] * inv_b, O[dt][3] * inv_b);
    }
}

// ---------------------------------------------------------------------------
// Fused (residual + NB split-K partials) add + LayerNorm over D=512.
// ---------------------------------------------------------------------------
template <int NB, bool SPLITOUT>
__global__ void __launch_bounds__(256)
add_ln(const float* __restrict__ A, const float* __restrict__ PS,
       const float* __restrict__ g, const float* __restrict__ be,
       float* __restrict__ out, bf16* __restrict__ oh, bf16* __restrict__ ol)
{
    __shared__ float sh[16];
    const int row = blockIdx.x;
    const int t   = threadIdx.x;
    const size_t base = (size_t)row * DMODEL;

    float v0 = A[base + t];
    float v1 = A[base + t + 256];
#pragma unroll
    for (int s = 0; s < NB; s++) {
        v0 += PS[(size_t)s * MTOT * DMODEL + base + t];
        v1 += PS[(size_t)s * MTOT * DMODEL + base + t + 256];
    }
    float s = v0 + v1;
    float q = v0 * v0 + v1 * v1;
#pragma unroll
    for (int ofs = 16; ofs; ofs >>= 1) {
        s += __shfl_xor_sync(0xffffffffu, s, ofs);
        q += __shfl_xor_sync(0xffffffffu, q, ofs);
    }
    if ((t & 31) == 0) { sh[t >> 5] = s; sh[8 + (t >> 5)] = q; }
    __syncthreads();
    if (t < 32) {
        s = (t < 8) ? sh[t]     : 0.f;
        q = (t < 8) ? sh[8 + t] : 0.f;
#pragma unroll
        for (int ofs = 4; ofs; ofs >>= 1) {
            s += __shfl_xor_sync(0xffffffffu, s, ofs);
            q += __shfl_xor_sync(0xffffffffu, q, ofs);
        }
        if (t == 0) {
            float mean = s * (1.f / DMODEL);
            float var  = q * (1.f / DMODEL) - mean * mean;
            sh[0] = mean;
            sh[1] = rsqrtf(var + LN_EPS);
        }
    }
    __syncthreads();
    float mean = sh[0], rstd = sh[1];
    float y0 = (v0 - mean) * rstd * g[t]       + be[t];
    float y1 = (v1 - mean) * rstd * g[t + 256] + be[t + 256];
    out[base + t]       = y0;
    out[base + t + 256] = y1;
    if (SPLITOUT) {
        float h0 = __bfloat162float(__float2bfloat16_rn(y0));
        float h1 = __bfloat162float(__float2bfloat16_rn(y1));
        oh[base + t]       = __float2bfloat16_rn(y0);
        ol[base + t]       = __float2bfloat16_rn(y0 - h0);
        oh[base + t + 256] = __float2bfloat16_rn(y1);
        ol[base + t + 256] = __float2bfloat16_rn(y1 - h1);
    }
}

// ---------------------------------------------------------------------------
// kernel_launch
// Inputs: x Wq bq Wk bk Wv bv Wo bo W1 b1 W2 b2 g1 be1 g2 be2
// ---------------------------------------------------------------------------
extern "C" void kernel_launch(void* const* d_in, const int* in_sizes, int n_in,
                              void* d_out, int out_size)
{
    const float* x   = (const float*)d_in[0];
    const float* Wq  = (const float*)d_in[1];
    const float* bq  = (const float*)d_in[2];
    const float* Wk  = (const float*)d_in[3];
    const float* bk  = (const float*)d_in[4];
    const float* Wv  = (const float*)d_in[5];
    const float* bv  = (const float*)d_in[6];
    const float* Wo  = (const float*)d_in[7];
    const float* bo  = (const float*)d_in[8];
    const float* W1  = (const float*)d_in[9];
    const float* b1  = (const float*)d_in[10];
    const float* W2  = (const float*)d_in[11];
    const float* b2  = (const float*)d_in[12];
    const float* g1  = (const float*)d_in[13];
    const float* be1 = (const float*)d_in[14];
    const float* g2  = (const float*)d_in[15];
    const float* be2 = (const float*)d_in[16];
    float* out = (float*)d_out;

    float *PS, *H;
    bf16 *Ch, *Cl, *Hh, *Hl, *Fh, *Fl;
    bf16 *Woh, *Wol, *W1h, *W1l, *W2h, *W2l;
    cudaGetSymbolAddress((void**)&PS,  g_PS);
    cudaGetSymbolAddress((void**)&H,   g_H);
    cudaGetSymbolAddress((void**)&Ch,  g_Ch);
    cudaGetSymbolAddress((void**)&Cl,  g_Cl);
    cudaGetSymbolAddress((void**)&Hh,  g_Hh);
    cudaGetSymbolAddress((void**)&Hl,  g_Hl);
    cudaGetSymbolAddress((void**)&Fh,  g_Fh);
    cudaGetSymbolAddress((void**)&Fl,  g_Fl);
    cudaGetSymbolAddress((void**)&Woh, g_Woh);
    cudaGetSymbolAddress((void**)&Wol, g_Wol);
    cudaGetSymbolAddress((void**)&W1h, g_W1h);
    cudaGetSymbolAddress((void**)&W1l, g_W1l);
    cudaGetSymbolAddress((void**)&W2h, g_W2h);
    cudaGetSymbolAddress((void**)&W2l, g_W2l);

    static bool attr_done = false;
    if (!attr_done) {
        cudaFuncSetAttribute(gemm_qkv_bias,
                             cudaFuncAttributeMaxDynamicSharedMemorySize, GEMM_SMEM);
        cudaFuncSetAttribute(gemm_sp<1, true>,
                             cudaFuncAttributeMaxDynamicSharedMemorySize, GEMM_SMEM);
        cudaFuncSetAttribute(gemm_splitk<4>,
                             cudaFuncAttributeMaxDynamicSharedMemorySize, GEMM_SMEM);
        cudaFuncSetAttribute(flash_attn_mma,
                             cudaFuncAttributeMaxDynamicSharedMemorySize, FA_SMEM);
        attr_done = true;
    }

    dim3 gqkv (DMODEL / 128, MTOT / 64, 3);   // 768 CTAs
    dim3 gwo  (DMODEL / 128, MTOT / 64, 4);   // 1024 CTAs (split-K=4)
    dim3 gff1 (DFF    / 128, MTOT / 64);      // 1024 CTAs
    dim3 gw2  (DMODEL / 128, MTOT / 64, 4);   // 1024 CTAs (split-K=4)

    // 0) split x + weights into bf16 hi/lo planes
    split_inputs<<<dim3(512, 7), 256>>>(x, Wq, Wk, Wv, Wo, W1, W2);

    // 1) QKV projections (Q pre-scaled by 1/8)
    gemm_qkv_bias<<<gqkv, 128, GEMM_SMEM>>>(bq, bk, bv);

    // 2) attention -> CTX planes (2 CTAs/SM guaranteed)
    flash_attn_mma<<<dim3(SEQ / 128, BATCH * NHEADS), 256, FA_SMEM>>>();

    // 3) output projection (split-K=4) -> PS[0..3]
    gemm_splitk<4><<<gwo, 128, GEMM_SMEM>>>(Ch, Cl, Woh, Wol, bo, PS,
                                            DMODEL, DMODEL);

    // 4) residual + 4 partials + LN1 -> H fp32 + planes
    add_ln<4, true><<<MTOT, 256>>>(x, PS, g1, be1, H, Hh, Hl);

    // 5) FFN up + ReLU -> FF planes
    gemm_sp<1, true><<<gff1, 128, GEMM_SMEM>>>(Hh, Hl, W1h, W1l, b1,
                                               nullptr, Fh, Fl, DFF, DMODEL);

    // 6) FFN down (split-K=4) -> PS[0..3]
    gemm_splitk<4><<<gw2, 128, GEMM_SMEM>>>(Fh, Fl, W2h, W2l, b2, PS,
                                            DMODEL, DFF);

    // 7) residual + 4 partials + LN2 -> out
    add_ln<4, false><<<MTOT, 256>>>(H, PS, g2, be2, out, nullptr, nullptr);
}